// round 17
// baseline (speedup 1.0000x reference)
#include <cuda_runtime.h>
#include <math.h>

#define SEQ_T 256
#define NB    1024
#define TBROWS (SEQ_T*NB)   // 262144

typedef unsigned long long ull;

// ---------------- scratch (__device__ globals; no allocation allowed) ----------------
__device__ float g_xw1[(size_t)TBROWS*256];   // fc1 input-GEMM gates (pad 240->256)

__device__ float g_Wpre1[128*256];
__device__ float g_b1[256];
__device__ float g_WhhT1[60*240];
__device__ float g_W21c[80*80];
__device__ float g_b21[80];
__device__ float g_W3[40*80];
__device__ float g_b3[80];
__device__ float g_W4a[824*2560];  // cols 0..2559, 4 zero pad rows
__device__ float g_W4b[832*640];   // cols 2560..3199, 12 zero pad rows (8-deep pipeline)
__device__ float g_b4[3200];
__device__ float g_W5[948*512];    // 20 zero pad rows (12-deep pipeline)
__device__ float g_b5[512];
__device__ float g_dWT[128*20];

__device__ float g_h21[NB*20], g_c21[NB*20];  // mu, c_mean

__device__ __forceinline__ float sigf(float x){ return 1.0f/(1.0f+expf(-x)); }

// fast activations for the decoder: 1 MUFU each (MUFU.TANH)
__device__ __forceinline__ float ftanh(float x){
    float r; asm("tanh.approx.f32 %0, %1;" : "=f"(r) : "f"(x)); return r;
}
__device__ __forceinline__ float fsig(float x){
    return 0.5f + 0.5f*ftanh(0.5f*x);
}

__device__ __forceinline__ ull dup2(float x){
    ull r; asm("mov.b64 %0, {%1, %1};" : "=l"(r) : "f"(x)); return r;
}
__device__ __forceinline__ void fma2(ull& d, ull a, ull b){
    asm("fma.rn.f32x2 %0, %1, %2, %0;" : "+l"(d) : "l"(a), "l"(b));
}
__device__ __forceinline__ ull add2(ull a, ull b){
    ull r; asm("add.rn.f32x2 %0, %1, %2;" : "=l"(r) : "l"(a), "l"(b)); return r;
}
__device__ __forceinline__ float2 unp2(ull v){
    float2 r; asm("mov.b64 {%0, %1}, %2;" : "=f"(r.x), "=f"(r.y) : "l"(v)); return r;
}

// group barrier: ids 1 and 2, 320 threads each
#define GBAR(gg) asm volatile("bar.sync %0, 320;" :: "r"((gg)+1) : "memory")

// ---------------- one-shot packing of all weights/biases ----------------
__global__ void pack_all_kernel(
    const float* __restrict__ fc1_Wih,  const float* __restrict__ fc1_Whh,
    const float* __restrict__ fc1_bih,  const float* __restrict__ fc1_bhh,
    const float* __restrict__ fc21_Wih, const float* __restrict__ fc21_Whh,
    const float* __restrict__ fc21_bih, const float* __restrict__ fc21_bhh,
    const float* __restrict__ l3_Wih,   const float* __restrict__ l3_Whh,
    const float* __restrict__ l3_bih,   const float* __restrict__ l3_bhh,
    const float* __restrict__ l4_Wih,   const float* __restrict__ l4_Whh,
    const float* __restrict__ l4_bih,   const float* __restrict__ l4_bhh,
    const float* __restrict__ l5_Wih,   const float* __restrict__ l5_Whh,
    const float* __restrict__ l5_bih,   const float* __restrict__ l5_bhh,
    const float* __restrict__ down_W)
{
    int g = blockIdx.x*blockDim.x + threadIdx.x;
    int stride = gridDim.x*blockDim.x;
    for (int idx=g; idx<820*2560; idx+=stride){
        int k = idx/2560, c = idx - k*2560;
        g_W4a[idx] = (k<20) ? l4_Wih[(size_t)c*20 + k] : l4_Whh[(size_t)c*800 + (k-20)];
    }
    for (int idx=g; idx<820*640; idx+=stride){
        int k = idx/640, c = idx - k*640;
        int col = 2560 + c;
        g_W4b[idx] = (k<20) ? l4_Wih[(size_t)col*20 + k] : l4_Whh[(size_t)col*800 + (k-20)];
    }
    for (int idx=g; idx<928*512; idx+=stride){
        int k = idx/512, c = idx - k*512;
        g_W5[idx] = (k<800) ? l5_Wih[(size_t)c*800 + k] : l5_Whh[(size_t)c*128 + (k-800)];
    }
    for (int idx=g; idx<4*2560;  idx+=stride) g_W4a[820*2560 + idx] = 0.f;
    for (int idx=g; idx<12*640;  idx+=stride) g_W4b[820*640  + idx] = 0.f;
    for (int idx=g; idx<20*512;  idx+=stride) g_W5[928*512 + idx]   = 0.f;
    for (int idx=g; idx<128*256; idx+=stride){
        int k = idx/256, c = idx - k*256;
        g_Wpre1[idx] = (c<240) ? fc1_Wih[(size_t)c*128 + k] : 0.f;
    }
    for (int idx=g; idx<60*240; idx+=stride){
        int k = idx/240, c = idx - k*240;
        g_WhhT1[idx] = fc1_Whh[(size_t)c*60 + k];
    }
    for (int idx=g; idx<80*80; idx+=stride){
        int k = idx/80, c = idx - k*80;
        g_W21c[idx] = (k<60) ? fc21_Wih[(size_t)c*60 + k] : fc21_Whh[(size_t)c*20 + (k-60)];
    }
    for (int idx=g; idx<40*80; idx+=stride){
        int k = idx/80, c = idx - k*80;
        g_W3[idx] = (k<20) ? l3_Wih[(size_t)c*20 + k] : l3_Whh[(size_t)c*20 + (k-20)];
    }
    for (int idx=g; idx<128*20; idx+=stride){
        int k = idx/20, j = idx - k*20;
        g_dWT[idx] = down_W[(size_t)j*128 + k];
    }
    for (int idx=g; idx<256;  idx+=stride) g_b1[idx]  = (idx<240) ? fc1_bih[idx]+fc1_bhh[idx] : 0.f;
    for (int idx=g; idx<80;   idx+=stride) g_b21[idx] = fc21_bih[idx]+fc21_bhh[idx];
    for (int idx=g; idx<80;   idx+=stride) g_b3[idx]  = l3_bih[idx]+l3_bhh[idx];
    for (int idx=g; idx<3200; idx+=stride) g_b4[idx]  = l4_bih[idx]+l4_bhh[idx];
    for (int idx=g; idx<512;  idx+=stride) g_b5[idx]  = l5_bih[idx]+l5_bhh[idx];
}

// ---------------- tiled SGEMM with bias: C = A(MxK) * B(KxN) + bias ----------------
template<int BM,int BN,int BK,int TM,int TN>
__global__ __launch_bounds__((BM/TM)*(BN/TN))
void sgemm_bias_kernel(const float* __restrict__ A,
                       const float* __restrict__ Bw,
                       const float* __restrict__ bias,
                       float* __restrict__ C,
                       int M, int N, int K)
{
    constexpr int TCOLS = BN/TN;
    constexpr int TROWS = BM/TM;
    constexpr int THREADS = TCOLS*TROWS;
    __shared__ float As[BK][BM];
    __shared__ float Bs[BK][BN];
    const int tid = threadIdx.x;
    const int bn = blockIdx.x * BN;
    const int bm = blockIdx.y * BM;
    const int tc = (tid % TCOLS)*TN;
    const int tr = (tid / TCOLS)*TM;

    float acc[TM][TN];
    #pragma unroll
    for (int i=0;i<TM;i++)
        #pragma unroll
        for (int j=0;j<TN;j++) acc[i][j]=0.f;

    constexpr int APER = (BM*BK/4)/THREADS;
    constexpr int BPER = (BK*BN/4)/THREADS;

    for (int k0 = 0; k0 < K; k0 += BK) {
        #pragma unroll
        for (int it=0; it<APER; it++){
            int f = tid + it*THREADS;
            int row = f / (BK/4);
            int kc  = (f % (BK/4))*4;
            float4 v = *reinterpret_cast<const float4*>(A + (size_t)(bm+row)*K + k0 + kc);
            As[kc+0][row]=v.x; As[kc+1][row]=v.y; As[kc+2][row]=v.z; As[kc+3][row]=v.w;
        }
        #pragma unroll
        for (int it=0; it<BPER; it++){
            int f = tid + it*THREADS;
            int kr = f / (BN/4);
            int nc = (f % (BN/4))*4;
            *reinterpret_cast<float4*>(&Bs[kr][nc]) =
                *reinterpret_cast<const float4*>(Bw + (size_t)(k0+kr)*N + bn + nc);
        }
        __syncthreads();
        #pragma unroll
        for (int kk=0;kk<BK;kk++){
            float a[TM], b[TN];
            #pragma unroll
            for (int i=0;i<TM;i+=4)
                *reinterpret_cast<float4*>(&a[i]) = *reinterpret_cast<const float4*>(&As[kk][tr+i]);
            #pragma unroll
            for (int j=0;j<TN;j+=4)
                *reinterpret_cast<float4*>(&b[j]) = *reinterpret_cast<const float4*>(&Bs[kk][tc+j]);
            #pragma unroll
            for (int i=0;i<TM;i++)
                #pragma unroll
                for (int j=0;j<TN;j++)
                    acc[i][j] = fmaf(a[i], b[j], acc[i][j]);
        }
        __syncthreads();
    }
    #pragma unroll
    for (int i=0;i<TM;i++){
        float* crow = C + (size_t)(bm+tr+i)*N + bn + tc;
        #pragma unroll
        for (int j=0;j<TN;j+=4){
            float4 v;
            v.x = acc[i][j+0] + bias[bn+tc+j+0];
            v.y = acc[i][j+1] + bias[bn+tc+j+1];
            v.z = acc[i][j+2] + bias[bn+tc+j+2];
            v.w = acc[i][j+3] + bias[bn+tc+j+3];
            *reinterpret_cast<float4*>(crow + j) = v;
        }
    }
}

// ---------------- fused encoder: all 256 steps of fc1 + fc21 per 8 batch rows ----------------
#define ENC_T 64
__global__ __launch_bounds__(ENC_T) void encoder_kernel(const float* __restrict__ xw1,
                                                        float* __restrict__ out)
{
    extern __shared__ float es[];
    float* Wh1  = es;            // 14400
    float* W21  = es + 14400;    // 6400
    float* b21  = es + 20800;    // 80
    float* h1s  = es + 20880;    // [60][8] 480
    float* h21s = es + 21360;    // [20][8] 160
    const int tid = threadIdx.x;
    const int b0  = blockIdx.x * 8;

    for (int i=tid; i<14400; i+=ENC_T) Wh1[i] = g_WhhT1[i];
    for (int i=tid; i<6400;  i+=ENC_T) W21[i] = g_W21c[i];
    for (int i=tid; i<80;    i+=ENC_T) b21[i] = g_b21[i];
    for (int i=tid; i<480;   i+=ENC_T) h1s[i] = 0.f;
    for (int i=tid; i<160;   i+=ENC_T) h21s[i] = 0.f;
    float c1r[8], c21r[8];
    #pragma unroll
    for (int r=0;r<8;r++){ c1r[r]=0.f; c21r[r]=0.f; }
    __syncthreads();

    for (int t=0; t<SEQ_T; t++){
        float nh[8];
        if (tid < 60){
            float a0[8],a1[8],a2[8],a3[8];
            #pragma unroll
            for (int r=0;r<8;r++){
                const float* xr = xw1 + ((size_t)t*NB + b0 + r)*256;
                a0[r]=xr[tid]; a1[r]=xr[60+tid]; a2[r]=xr[120+tid]; a3[r]=xr[180+tid];
            }
            for (int k=0;k<60;k++){
                float w0=Wh1[k*240+tid], w1=Wh1[k*240+60+tid],
                      w2=Wh1[k*240+120+tid], w3=Wh1[k*240+180+tid];
                #pragma unroll
                for (int r=0;r<8;r++){
                    float hv=h1s[k*8+r];
                    a0[r]=fmaf(hv,w0,a0[r]); a1[r]=fmaf(hv,w1,a1[r]);
                    a2[r]=fmaf(hv,w2,a2[r]); a3[r]=fmaf(hv,w3,a3[r]);
                }
            }
            #pragma unroll
            for (int r=0;r<8;r++){
                float cv = sigf(a1[r])*c1r[r] + sigf(a0[r])*tanhf(a2[r]);
                c1r[r]=cv;
                nh[r] = sigf(a3[r])*tanhf(cv);
            }
        }
        __syncthreads();
        if (tid < 60){
            #pragma unroll
            for (int r=0;r<8;r++) h1s[tid*8+r]=nh[r];
        }
        __syncthreads();
        if (tid < 20){
            float a0[8],a1[8],a2[8],a3[8];
            #pragma unroll
            for (int r=0;r<8;r++){
                a0[r]=b21[tid]; a1[r]=b21[20+tid]; a2[r]=b21[40+tid]; a3[r]=b21[60+tid];
            }
            for (int k=0;k<60;k++){
                float w0=W21[k*80+tid], w1=W21[k*80+20+tid],
                      w2=W21[k*80+40+tid], w3=W21[k*80+60+tid];
                #pragma unroll
                for (int r=0;r<8;r++){
                    float xv=fmaxf(h1s[k*8+r],0.f);
                    a0[r]=fmaf(xv,w0,a0[r]); a1[r]=fmaf(xv,w1,a1[r]);
                    a2[r]=fmaf(xv,w2,a2[r]); a3[r]=fmaf(xv,w3,a3[r]);
                }
            }
            for (int k=0;k<20;k++){
                float w0=W21[(60+k)*80+tid], w1=W21[(60+k)*80+20+tid],
                      w2=W21[(60+k)*80+40+tid], w3=W21[(60+k)*80+60+tid];
                #pragma unroll
                for (int r=0;r<8;r++){
                    float hv=h21s[k*8+r];
                    a0[r]=fmaf(hv,w0,a0[r]); a1[r]=fmaf(hv,w1,a1[r]);
                    a2[r]=fmaf(hv,w2,a2[r]); a3[r]=fmaf(hv,w3,a3[r]);
                }
            }
            #pragma unroll
            for (int r=0;r<8;r++){
                float cv = sigf(a1[r])*c21r[r] + sigf(a0[r])*tanhf(a2[r]);
                c21r[r]=cv;
                nh[r] = sigf(a3[r])*tanhf(cv);
            }
        }
        __syncthreads();
        if (tid < 20){
            #pragma unroll
            for (int r=0;r<8;r++) h21s[tid*8+r]=nh[r];
        }
        __syncthreads();
    }
    if (tid < 20){
        #pragma unroll
        for (int r=0;r<8;r++){
            int b = b0 + r;
            float mu = h21s[tid*8+r];
            g_h21[(size_t)b*20 + tid] = mu;
            g_c21[(size_t)b*20 + tid] = c21r[r];
            out[(size_t)SEQ_T*NB*128 + (size_t)b*20 + tid] = mu;
        }
    }
}

// ---------------- fused decoder: two independent 4-row groups per block ----------------
// Per-group smem block (21008 floats):
//  xh4s [956][4] 3824 @0  (rows: 0..19 h_l3 | 20..819 h2 | 820..947 h3 mirror | 948..955 zero)
//  g4s  [3200][4] 12800 @3824 (l4 gates; reused for l5 gates [512][4])
//  c2s 3200 @16624 | h3s 512 @19824 | c3s 512 @20336 | c3ls 80 @20848 | oins 80 @20928
// Shared (read-only): W3s 3200 @42016 | dWTs 2560 @45216 | b3s 80 @47776 | b4s 3200 @47856
//                     b5s 512 @51056 | dbs 20 @51568  -> total 51588 floats
#define DEC_T 640
#define GRP_FLOATS 21008
#define DEC_SMEM_FLOATS 51588
__global__ __launch_bounds__(DEC_T,1) void decoder_kernel(const float* __restrict__ idW,
                                                          const float* __restrict__ idb,
                                                          const float* __restrict__ down_b,
                                                          float* __restrict__ out)
{
    extern __shared__ float ds[];
    float* W3s  = ds + 42016;
    float* dWTs = ds + 45216;
    float* b3s  = ds + 47776;
    float* b4s  = ds + 47856;
    float* b5s  = ds + 51056;
    float* dbs  = ds + 51568;

    const int tid = threadIdx.x;

    // block-wide init
    for (int i=tid; i<42016; i+=DEC_T) ds[i] = 0.f;      // both group blocks
    for (int i=tid; i<3200; i+=DEC_T) W3s[i]  = g_W3[i];
    for (int i=tid; i<2560; i+=DEC_T) dWTs[i] = g_dWT[i];
    for (int i=tid; i<80;   i+=DEC_T) b3s[i]  = g_b3[i];
    for (int i=tid; i<3200; i+=DEC_T) b4s[i]  = g_b4[i];
    for (int i=tid; i<512;  i+=DEC_T) b5s[i]  = g_b5[i];
    for (int i=tid; i<20;   i+=DEC_T) dbs[i]  = down_b[i];
    __syncthreads();

    const int g  = tid / 320;        // group 0: warps 0-9, group 1: warps 10-19
    const int lt = tid - g*320;
    float* gb   = ds + g*GRP_FLOATS;
    float* xh4s = gb;
    float* g4s  = gb + 3824;
    float* c2s  = gb + 16624;
    float* h3s  = gb + 19824;
    float* c3s  = gb + 20336;
    float* c3ls = gb + 20848;
    float* oins = gb + 20928;
    const int b0 = blockIdx.x*8 + g*4;

    if (lt < 80){
        int j = lt>>2, r = lt&3, b = b0 + r;
        xh4s[j*4+r] = g_h21[(size_t)b*20 + j];
        c3ls[j*4+r] = g_c21[(size_t)b*20 + j];
        float acc = idb[j];
        for (int k=0;k<20;k++) acc = fmaf(g_h21[(size_t)b*20 + k], idW[j*20+k], acc);
        oins[j*4+r] = acc;
    }
    GBAR(g);

    for (int t=0; t<SEQ_T; t++){
        // ---- l3 cell (20x20, 80 threads) ----
        float nh3l=0.f, nc3l=0.f;
        if (lt < 80){
            int j = lt>>2, r = lt&3;
            float a0=b3s[j], a1=b3s[20+j], a2=b3s[40+j], a3=b3s[60+j];
            #pragma unroll
            for (int k=0;k<20;k++){
                float x = oins[k*4+r];
                a0=fmaf(x,W3s[k*80+j],a0);    a1=fmaf(x,W3s[k*80+20+j],a1);
                a2=fmaf(x,W3s[k*80+40+j],a2); a3=fmaf(x,W3s[k*80+60+j],a3);
            }
            #pragma unroll
            for (int k=0;k<20;k++){
                float x = xh4s[k*4+r];
                a0=fmaf(x,W3s[(20+k)*80+j],a0);    a1=fmaf(x,W3s[(20+k)*80+20+j],a1);
                a2=fmaf(x,W3s[(20+k)*80+40+j],a2); a3=fmaf(x,W3s[(20+k)*80+60+j],a3);
            }
            nc3l = fsig(a1)*c3ls[(lt>>2)*4+(lt&3)] + fsig(a0)*ftanh(a2);
            nh3l = fsig(a3)*ftanh(nc3l);
        }
        GBAR(g);
        if (lt < 80){ int j=lt>>2, r=lt&3; xh4s[j*4+r]=nh3l; c3ls[j*4+r]=nc3l; }
        GBAR(g);

        // ---- l4 GEMM pass A: cols 0..2559 (8 per thread, W4a) ----
        {
            const int c8 = lt*8;
            ull acc[8][2];   // [col][rowpair]
            #pragma unroll
            for (int c=0;c<8;c++){ acc[c][0]=0ull; acc[c][1]=0ull; }
            const float* wpa = g_W4a + c8;

            #define L4A(W0, W1, KK) { \
                const ull* xk = reinterpret_cast<const ull*>(xh4s + (size_t)(KK)*4); \
                ull x0=xk[0], x1=xk[1]; \
                ull a0=dup2(W0.x), a1=dup2(W0.y), a2=dup2(W0.z), a3=dup2(W0.w); \
                ull a4=dup2(W1.x), a5=dup2(W1.y), a6=dup2(W1.z), a7=dup2(W1.w); \
                fma2(acc[0][0],a0,x0); fma2(acc[0][1],a0,x1); \
                fma2(acc[1][0],a1,x0); fma2(acc[1][1],a1,x1); \
                fma2(acc[2][0],a2,x0); fma2(acc[2][1],a2,x1); \
                fma2(acc[3][0],a3,x0); fma2(acc[3][1],a3,x1); \
                fma2(acc[4][0],a4,x0); fma2(acc[4][1],a4,x1); \
                fma2(acc[5][0],a5,x0); fma2(acc[5][1],a5,x1); \
                fma2(acc[6][0],a6,x0); fma2(acc[6][1],a6,x1); \
                fma2(acc[7][0],a7,x0); fma2(acc[7][1],a7,x1); }

            float4 wa0 = *reinterpret_cast<const float4*>(wpa);
            float4 wa1 = *reinterpret_cast<const float4*>(wpa + 4);
            float4 wb0 = *reinterpret_cast<const float4*>(wpa + 2560);
            float4 wb1 = *reinterpret_cast<const float4*>(wpa + 2564);
            for (int k=0; k<820; k+=4){
                const float* wk = wpa + (size_t)k*2560;
                float4 wc0 = *reinterpret_cast<const float4*>(wk + 2*2560);
                float4 wc1 = *reinterpret_cast<const float4*>(wk + 2*2560 + 4);
                float4 wd0 = *reinterpret_cast<const float4*>(wk + 3*2560);
                float4 wd1 = *reinterpret_cast<const float4*>(wk + 3*2560 + 4);
                L4A(wa0, wa1, k);
                L4A(wb0, wb1, k+1);
                wa0 = *reinterpret_cast<const float4*>(wk + 4*2560);
                wa1 = *reinterpret_cast<const float4*>(wk + 4*2560 + 4);
                wb0 = *reinterpret_cast<const float4*>(wk + 5*2560);
                wb1 = *reinterpret_cast<const float4*>(wk + 5*2560 + 4);
                L4A(wc0, wc1, k+2);
                L4A(wd0, wd1, k+3);
            }
            #undef L4A
            #pragma unroll
            for (int c=0;c<8;c++){
                int col = c8 + c;
                ull b2 = dup2(b4s[col]);
                *reinterpret_cast<ull*>(&g4s[(size_t)col*4 + 0]) = add2(acc[c][0], b2);
                *reinterpret_cast<ull*>(&g4s[(size_t)col*4 + 2]) = add2(acc[c][1], b2);
            }
        }
        // ---- l4 GEMM pass B: cols 2560..3199 (2 per thread, W4b, 8-deep rotating) ----
        {
            const int cb = lt*2;
            const int colb = 2560 + cb;
            ull acc[2][2];
            acc[0][0]=0ull; acc[0][1]=0ull; acc[1][0]=0ull; acc[1][1]=0ull;
            const float* wpb = g_W4b + cb;
            float2 w[8];
            #pragma unroll
            for (int i=0;i<8;i++) w[i] = *reinterpret_cast<const float2*>(wpb + (size_t)i*640);
            for (int k=0; k<824; k+=8){
                #pragma unroll
                for (int i=0;i<8;i++){
                    const ull* xk = reinterpret_cast<const ull*>(xh4s + (size_t)(k+i)*4);
                    ull x0=xk[0], x1=xk[1];
                    float2 wv = w[i];
                    w[i] = *reinterpret_cast<const float2*>(wpb + (size_t)(k+8+i)*640);
                    ull w0=dup2(wv.x), w1=dup2(wv.y);
                    fma2(acc[0][0],w0,x0); fma2(acc[0][1],w0,x1);
                    fma2(acc[1][0],w1,x0); fma2(acc[1][1],w1,x1);
                }
            }
            #pragma unroll
            for (int c=0;c<2;c++){
                ull b2 = dup2(b4s[colb+c]);
                *reinterpret_cast<ull*>(&g4s[(size_t)(colb+c)*4 + 0]) = add2(acc[c][0], b2);
                *reinterpret_cast<ull*>(&g4s[(size_t)(colb+c)*4 + 2]) = add2(acc[c][1], b2);
            }
        }
        GBAR(g);

        // ---- l4 pointwise: update c2, write new h2 into xh4s rows 20..819 ----
        for (int m=lt; m<3200; m+=320){
            int j = m>>2, r = m&3;
            float gi = g4s[j*4+r];
            float gf = g4s[(800+j)*4+r];
            float gg = g4s[(1600+j)*4+r];
            float go = g4s[(2400+j)*4+r];
            float cv = fsig(gf)*c2s[m] + fsig(gi)*ftanh(gg);
            float hv = fsig(go)*ftanh(cv);
            c2s[m] = cv;
            xh4s[(20+j)*4+r] = hv;
        }
        GBAR(g);

        // ---- l5 GEMM: gates5[512] = xh4s rows 20..947 @ W5 (256 thr x 2 cols, 12-deep) ----
        if (lt < 256){
            const int c = lt*2;
            ull acc[4];
            acc[0]=0ull; acc[1]=0ull; acc[2]=0ull; acc[3]=0ull;
            const float* wp = g_W5 + c;
            ull w[12];
            #pragma unroll
            for (int i=0;i<12;i++)
                w[i] = *reinterpret_cast<const ull*>(wp + (size_t)i*512);
            for (int k=0; k<936; k+=12){
                #pragma unroll
                for (int i=0;i<12;i++){
                    const float* xk = xh4s + (size_t)(20+k+i)*4;
                    float4 xa = *reinterpret_cast<const float4*>(xk);
                    ull wv = w[i];
                    w[i] = *reinterpret_cast<const ull*>(wp + (size_t)(k+12+i)*512);
                    fma2(acc[0],wv,dup2(xa.x)); fma2(acc[1],wv,dup2(xa.y));
                    fma2(acc[2],wv,dup2(xa.z)); fma2(acc[3],wv,dup2(xa.w));
                }
            }
            float bA=b5s[c], bB=b5s[c+1];
            #pragma unroll
            for (int r=0;r<4;r++){
                float2 v = unp2(acc[r]);
                g4s[(size_t)c*4 + r]     = v.x + bA;
                g4s[(size_t)(c+1)*4 + r] = v.y + bB;
            }
        }
        GBAR(g);

        // ---- l5 pointwise: update c3, h3 (+ mirror); write output slice ----
        for (int m=lt; m<512; m+=320){
            int j = m>>2, r = m&3;
            float gi = g4s[j*4+r];
            float gf = g4s[(128+j)*4+r];
            float gg = g4s[(256+j)*4+r];
            float go = g4s[(384+j)*4+r];
            float cv = fsig(gf)*c3s[m] + fsig(gi)*ftanh(gg);
            float hv = fsig(go)*ftanh(cv);
            c3s[m] = cv;
            h3s[m] = hv;
            xh4s[(820+j)*4+r] = hv;
            out[(size_t)t*NB*128 + (size_t)(b0+r)*128 + j] = hv;
        }
        GBAR(g);

        // ---- down projection: out_in = h3(new) @ down_W.T + down_b (4-way ILP) ----
        if (lt < 80){
            int j = lt>>2, r = lt&3;
            float a0=dbs[j], a1=0.f, a2=0.f, a3=0.f;
            #pragma unroll
            for (int k=0;k<128;k+=4){
                a0 = fmaf(h3s[(k+0)*4+r], dWTs[(k+0)*20+j], a0);
                a1 = fmaf(h3s[(k+1)*4+r], dWTs[(k+1)*20+j], a1);
                a2 = fmaf(h3s[(k+2)*4+r], dWTs[(k+2)*20+j], a2);
                a3 = fmaf(h3s[(k+3)*4+r], dWTs[(k+3)*20+j], a3);
            }
            oins[j*4+r] = (a0+a1) + (a2+a3);
        }
        GBAR(g);
    }
}

// ---------------- launch: 4 graph nodes total ----------------
extern "C" void kernel_launch(void* const* d_in, const int* in_sizes, int n_in,
                              void* d_out, int out_size)
{
    const float* x        = (const float*)d_in[0];
    const float* fc1_Wih  = (const float*)d_in[1];
    const float* fc1_Whh  = (const float*)d_in[2];
    const float* fc1_bih  = (const float*)d_in[3];
    const float* fc1_bhh  = (const float*)d_in[4];
    const float* fc21_Wih = (const float*)d_in[5];
    const float* fc21_Whh = (const float*)d_in[6];
    const float* fc21_bih = (const float*)d_in[7];
    const float* fc21_bhh = (const float*)d_in[8];
    const float* l3_Wih   = (const float*)d_in[9];
    const float* l3_Whh   = (const float*)d_in[10];
    const float* l3_bih   = (const float*)d_in[11];
    const float* l3_bhh   = (const float*)d_in[12];
    const float* l4_Wih   = (const float*)d_in[13];
    const float* l4_Whh   = (const float*)d_in[14];
    const float* l4_bih   = (const float*)d_in[15];
    const float* l4_bhh   = (const float*)d_in[16];
    const float* l5_Wih   = (const float*)d_in[17];
    const float* l5_Whh   = (const float*)d_in[18];
    const float* l5_bih   = (const float*)d_in[19];
    const float* l5_bhh   = (const float*)d_in[20];
    const float* id_W     = (const float*)d_in[21];
    const float* id_b     = (const float*)d_in[22];
    const float* down_W   = (const float*)d_in[23];
    const float* down_b   = (const float*)d_in[24];
    float* out = (float*)d_out;

    float *xw1, *Wpre1, *b1;
    { void* p=nullptr; cudaGetSymbolAddress(&p, g_xw1);   xw1  =(float*)p; }
    { void* p=nullptr; cudaGetSymbolAddress(&p, g_Wpre1); Wpre1=(float*)p; }
    { void* p=nullptr; cudaGetSymbolAddress(&p, g_b1);    b1   =(float*)p; }

    cudaFuncSetAttribute(encoder_kernel, cudaFuncAttributeMaxDynamicSharedMemorySize, 21520*4);
    cudaFuncSetAttribute(decoder_kernel, cudaFuncAttributeMaxDynamicSharedMemorySize, DEC_SMEM_FLOATS*4);

    pack_all_kernel<<<512, 256>>>(fc1_Wih, fc1_Whh, fc1_bih, fc1_bhh,
                                  fc21_Wih, fc21_Whh, fc21_bih, fc21_bhh,
                                  l3_Wih, l3_Whh, l3_bih, l3_bhh,
                                  l4_Wih, l4_Whh, l4_bih, l4_bhh,
                                  l5_Wih, l5_Whh, l5_bih, l5_bhh,
                                  down_W);
    sgemm_bias_kernel<64,64,16,8,4><<<dim3(256/64, TBROWS/64), 128>>>(x, Wpre1, b1, xw1,
                                                                      TBROWS, 256, 128);
    encoder_kernel<<<NB/8, ENC_T, 21520*4>>>(xw1, out);
    decoder_kernel<<<NB/8, DEC_T, DEC_SMEM_FLOATS*4>>>(id_W, id_b, down_b, out);
}